// round 12
// baseline (speedup 1.0000x reference)
#include <cuda.h>
#include <cuda_runtime.h>
#include <cuda_fp16.h>
#include <cstdint>

// ---------------- problem sizes ----------------
#define MM 8192
#define NN 4096
#define KK 4096
#define GRP 64

#define BM 128
#define BN 128
#define BK 64
#define NSTAGE 3
#define KITER (KK / BK)          // 64 tiles, consumed in 32 pairs

#define A_BYTES (BM * BK * 2)    // 16384
#define B_BYTES (BN * BK * 2)    // 16384
#define STG_BYTES (A_BYTES + B_BYTES)   // 32768

#define SM_ALPHA 0               /* 128 floats */
#define SM_BARS 512              /* NSTAGE full barriers, 8B each */
#define SM_TILE 1024
#define SMEM_TOTAL (SM_TILE + NSTAGE * STG_BYTES)   /* 99328 -> 2 CTAs/SM */

#define XBLOCKS 16384            /* quant blocks handling x */
#define QBLOCKS (XBLOCKS + NN)   /* + one block per W row */

// ---------------- scratch (no allocations allowed) ----------------
__device__ __align__(1024) __half g_xq[(size_t)MM * KK];   // 64 MB
__device__ __align__(1024) __half g_ws[(size_t)NN * KK];   // 32 MB
__device__ float g_alpha[NN];

// ---------------- PTX helpers (plain sm_90-level features only) ----------------
__device__ __forceinline__ uint32_t smem_u32(const void* p) {
    uint32_t a;
    asm("{ .reg .u64 t; cvta.to.shared.u64 t, %1; cvt.u32.u64 %0, t; }" : "=r"(a) : "l"(p));
    return a;
}
__device__ __forceinline__ void mbar_init(uint32_t a, uint32_t c) {
    asm volatile("mbarrier.init.shared.b64 [%0], %1;" :: "r"(a), "r"(c) : "memory");
}
__device__ __forceinline__ void mbar_expect(uint32_t a, uint32_t bytes) {
    asm volatile("mbarrier.arrive.expect_tx.shared.b64 _, [%0], %1;" :: "r"(a), "r"(bytes) : "memory");
}
__device__ __forceinline__ void mbar_wait(uint32_t a, uint32_t p) {
    asm volatile(
        "{\n\t.reg .pred P;\n\t"
        "WL%=:\n\t"
        "mbarrier.try_wait.parity.acquire.cta.shared::cta.b64 P, [%0], %1, 0x989680;\n\t"
        "@P bra.uni WD%=;\n\t"
        "bra.uni WL%=;\n\t"
        "WD%=:\n\t}"
        :: "r"(a), "r"(p) : "memory");
}
__device__ __forceinline__ void tma_load_2d(uint32_t smem_addr, const void* map,
                                            int cx, int cy, uint32_t mbar) {
    asm volatile(
        "cp.async.bulk.tensor.2d.shared::cta.global.tile.mbarrier::complete_tx::bytes "
        "[%0], [%1, {%2, %3}], [%4];"
        :: "r"(smem_addr), "l"(map), "r"(cx), "r"(cy), "r"(mbar) : "memory");
}
__device__ __forceinline__ void ldsm_x4(uint32_t addr, uint32_t* r) {
    asm volatile("ldmatrix.sync.aligned.m8n8.x4.shared.b16 {%0,%1,%2,%3}, [%4];"
                 : "=r"(r[0]), "=r"(r[1]), "=r"(r[2]), "=r"(r[3]) : "r"(addr));
}
__device__ __forceinline__ void mma16816(float* c, const uint32_t* a, const uint32_t* b) {
    asm volatile(
        "mma.sync.aligned.m16n8k16.row.col.f32.f16.f16.f32 "
        "{%0,%1,%2,%3}, {%4,%5,%6,%7}, {%8,%9}, {%0,%1,%2,%3};"
        : "+f"(c[0]), "+f"(c[1]), "+f"(c[2]), "+f"(c[3])
        : "r"(a[0]), "r"(a[1]), "r"(a[2]), "r"(a[3]), "r"(b[0]), "r"(b[1]));
}

__device__ __forceinline__ float sgnf(float c) { return (c > 0.f) ? 1.f : ((c < 0.f) ? -1.f : 0.f); }
__device__ __forceinline__ float warp_sum(float v) {
#pragma unroll
    for (int o = 16; o > 0; o >>= 1) v += __shfl_xor_sync(0xFFFFFFFFu, v, o);
    return v;
}

// ---------------- fused quant kernel: x-groups (blocks < XBLOCKS) + W rows ----------------
__global__ void __launch_bounds__(256) quant_fused_kernel(const float* __restrict__ x,
                                                          const float* __restrict__ W) {
    if (blockIdx.x < XBLOCKS) {
        // ---- group-64 absmax fake-quant of x -> fp16 (8 threads/group, 8 floats/thread) ----
        uint32_t t = blockIdx.x * 256u + threadIdx.x;
        size_t base = (size_t)(t >> 3) * GRP + (size_t)(t & 7) * 8;
        float4 a = *reinterpret_cast<const float4*>(x + base);
        float4 b = *reinterpret_cast<const float4*>(x + base + 4);
        float am = fmaxf(fmaxf(fmaxf(fabsf(a.x), fabsf(a.y)), fmaxf(fabsf(a.z), fabsf(a.w))),
                         fmaxf(fmaxf(fabsf(b.x), fabsf(b.y)), fmaxf(fabsf(b.z), fabsf(b.w))));
        am = fmaxf(am, __shfl_xor_sync(0xFFFFFFFFu, am, 1));
        am = fmaxf(am, __shfl_xor_sync(0xFFFFFFFFu, am, 2));
        am = fmaxf(am, __shfl_xor_sync(0xFFFFFFFFu, am, 4));
        float s = fmaxf(am, 1e-8f);
        float inv = __fdividef(127.0f, s);
        float sc = s * (1.0f / 127.0f);
        __half2 h0 = __floats2half2_rn(rintf(a.x * inv) * sc, rintf(a.y * inv) * sc);
        __half2 h1 = __floats2half2_rn(rintf(a.z * inv) * sc, rintf(a.w * inv) * sc);
        __half2 h2 = __floats2half2_rn(rintf(b.x * inv) * sc, rintf(b.y * inv) * sc);
        __half2 h3 = __floats2half2_rn(rintf(b.z * inv) * sc, rintf(b.w * inv) * sc);
        uint4 u;
        u.x = *reinterpret_cast<uint32_t*>(&h0);
        u.y = *reinterpret_cast<uint32_t*>(&h1);
        u.z = *reinterpret_cast<uint32_t*>(&h2);
        u.w = *reinterpret_cast<uint32_t*>(&h3);
        *reinterpret_cast<uint4*>(g_xq + base) = u;
    } else {
        // ---- per-row W binarize (centered sign) + alpha ----
        const int row = blockIdx.x - XBLOCKS;
        const int tid = threadIdx.x;
        const float4* wr = reinterpret_cast<const float4*>(W + (size_t)row * KK);
        float4 v[4];
        float s = 0.f;
#pragma unroll
        for (int i = 0; i < 4; i++) {
            v[i] = wr[i * 256 + tid];
            s += (v[i].x + v[i].y) + (v[i].z + v[i].w);
        }
        __shared__ float red[8];
        s = warp_sum(s);
        if ((tid & 31) == 0) red[tid >> 5] = s;
        __syncthreads();
        float mean = (red[0] + red[1] + red[2] + red[3] +
                      red[4] + red[5] + red[6] + red[7]) * (1.0f / 4096.0f);
        __syncthreads();
        float sa = 0.f;
#pragma unroll
        for (int i = 0; i < 4; i++)
            sa += (fabsf(v[i].x - mean) + fabsf(v[i].y - mean)) +
                  (fabsf(v[i].z - mean) + fabsf(v[i].w - mean));
        sa = warp_sum(sa);
        if ((tid & 31) == 0) red[tid >> 5] = sa;
        __syncthreads();
        if (tid == 0)
            g_alpha[row] = (red[0] + red[1] + red[2] + red[3] +
                            red[4] + red[5] + red[6] + red[7]) * (1.0f / 4096.0f);
        __half* wrow = g_ws + (size_t)row * KK;
#pragma unroll
        for (int i = 0; i < 4; i++) {
            __half2 h0 = __floats2half2_rn(sgnf(v[i].x - mean), sgnf(v[i].y - mean));
            __half2 h1 = __floats2half2_rn(sgnf(v[i].z - mean), sgnf(v[i].w - mean));
            uint2 u;
            u.x = *reinterpret_cast<uint32_t*>(&h0);
            u.y = *reinterpret_cast<uint32_t*>(&h1);
            *reinterpret_cast<uint2*>(wrow + (size_t)(i * 256 + tid) * 4) = u;
        }
    }
}

// ---------------- kernel 3: TMA-pipelined mma.sync f16 GEMM, paired-sync ring ----------------
__global__ void __launch_bounds__(256, 2)
bitlinear_gemm(const __grid_constant__ CUtensorMap mapA,
               const __grid_constant__ CUtensorMap mapB,
               float* __restrict__ out) {
    extern __shared__ char smem[];
    const uint32_t sb = smem_u32(smem);
    const int tid = threadIdx.x;
    const int l = tid & 31;
    const int w = tid >> 5;
    const int wm = w & 3;       // 4 warps along M (32 rows each)
    const int wn = w >> 2;      // 2 warps along N (64 cols each)
    const int n0 = blockIdx.x * BN;
    const int m0 = blockIdx.y * BM;

    if (tid < 128)
        reinterpret_cast<float*>(smem + SM_ALPHA)[tid] = g_alpha[n0 + tid];
    if (tid == 0) {
#pragma unroll
        for (int s = 0; s < NSTAGE; s++) mbar_init(sb + SM_BARS + 8 * s, 1);
    }
    __syncthreads();

    // prologue: fill all 3 stages with tiles 0,1,2
    if (tid == 0) {
#pragma unroll
        for (int t = 0; t < NSTAGE; t++) {
            mbar_expect(sb + SM_BARS + 8 * t, STG_BYTES);
            uint32_t dst = sb + SM_TILE + t * STG_BYTES;
            tma_load_2d(dst,           &mapA, t * BK, m0, sb + SM_BARS + 8 * t);
            tma_load_2d(dst + A_BYTES, &mapB, t * BK, n0, sb + SM_BARS + 8 * t);
        }
    }

    // per-thread ldmatrix address precompute (SW128 swizzle XOR = (row&7)<<4)
    uint32_t aRow[2], aXor[2];
#pragma unroll
    for (int mi = 0; mi < 2; mi++) {
        int r = wm * 32 + mi * 16 + (l & 15);
        aRow[mi] = (uint32_t)r * 128u;
        aXor[mi] = (uint32_t)(r & 7) << 4;
    }
    const uint32_t akb = (uint32_t)(l >> 4) * 16u;
    const int g = l >> 3;
    uint32_t bRow[4], bXor[4];
#pragma unroll
    for (int nj4 = 0; nj4 < 4; nj4++) {
        int r = wn * 64 + nj4 * 16 + ((g >> 1) << 3) + (l & 7);
        bRow[nj4] = (uint32_t)r * 128u;
        bXor[nj4] = (uint32_t)(r & 7) << 4;
    }
    const uint32_t bkb = (uint32_t)(g & 1) * 16u;

    float acc[2][8][4];
#pragma unroll
    for (int mi = 0; mi < 2; mi++)
#pragma unroll
        for (int nj = 0; nj < 8; nj++)
#pragma unroll
            for (int c = 0; c < 4; c++) acc[mi][nj][c] = 0.f;

    // consume tiles in pairs; both waits hoisted to pair top; one __syncthreads per pair
    for (int p = 0; p < KITER / 2; p++) {
        const int t0 = 2 * p;
        const int s0 = t0 % NSTAGE;
        const int s1 = (t0 + 1) % NSTAGE;
        // hoisted waits: both stages of this pair (second is usually already full)
        mbar_wait(sb + SM_BARS + 8 * s0, (uint32_t)((t0 / NSTAGE) & 1));
        mbar_wait(sb + SM_BARS + 8 * s1, (uint32_t)(((t0 + 1) / NSTAGE) & 1));
#pragma unroll
        for (int h = 0; h < 2; h++) {
            const uint32_t ab = sb + SM_TILE + ((h == 0) ? s0 : s1) * STG_BYTES;
            const uint32_t bb = ab + A_BYTES;
#pragma unroll
            for (int ks = 0; ks < BK / 16; ks++) {
                uint32_t af[2][4], bf[4][4];
#pragma unroll
                for (int mi = 0; mi < 2; mi++)
                    ldsm_x4(ab + aRow[mi] + (((uint32_t)ks * 32u + akb) ^ aXor[mi]), af[mi]);
#pragma unroll
                for (int nj4 = 0; nj4 < 4; nj4++)
                    ldsm_x4(bb + bRow[nj4] + (((uint32_t)ks * 32u + bkb) ^ bXor[nj4]), bf[nj4]);
#pragma unroll
                for (int mi = 0; mi < 2; mi++)
#pragma unroll
                    for (int nj4 = 0; nj4 < 4; nj4++) {
                        mma16816(acc[mi][2 * nj4 + 0], af[mi], &bf[nj4][0]);
                        mma16816(acc[mi][2 * nj4 + 1], af[mi], &bf[nj4][2]);
                    }
            }
        }
        __syncthreads();   // stages of tiles 2p, 2p+1 now free
        if (tid == 0) {
#pragma unroll
            for (int h = 3; h <= 4; h++) {
                const int nt = 2 * p + h;       // tiles 2p+3, 2p+4
                if (nt < KITER) {
                    const int sn = nt % NSTAGE;
                    mbar_expect(sb + SM_BARS + 8 * sn, STG_BYTES);
                    uint32_t dst = sb + SM_TILE + sn * STG_BYTES;
                    tma_load_2d(dst,           &mapA, nt * BK, m0, sb + SM_BARS + 8 * sn);
                    tma_load_2d(dst + A_BYTES, &mapB, nt * BK, n0, sb + SM_BARS + 8 * sn);
                }
            }
        }
    }

    // ---- epilogue: scale by alpha[n], store fp32 ----
    const float* al = reinterpret_cast<const float*>(smem + SM_ALPHA);
    const int q = l >> 2, t4 = l & 3;
#pragma unroll
    for (int mi = 0; mi < 2; mi++) {
#pragma unroll
        for (int nj = 0; nj < 8; nj++) {
            const int nloc = wn * 64 + nj * 8 + t4 * 2;
            const float a0 = al[nloc], a1 = al[nloc + 1];
            const size_t r0 = (size_t)(m0 + wm * 32 + mi * 16 + q) * NN + n0 + nloc;
            float2 v0, v1;
            v0.x = acc[mi][nj][0] * a0; v0.y = acc[mi][nj][1] * a1;
            v1.x = acc[mi][nj][2] * a0; v1.y = acc[mi][nj][3] * a1;
            *reinterpret_cast<float2*>(out + r0) = v0;
            *reinterpret_cast<float2*>(out + r0 + 8 * NN) = v1;
        }
    }
}

// ---------------- host launch ----------------
typedef CUresult (*PFN_tmEncode)(CUtensorMap*, CUtensorMapDataType, cuuint32_t, void*,
                                 const cuuint64_t*, const cuuint64_t*, const cuuint32_t*,
                                 const cuuint32_t*, CUtensorMapInterleave, CUtensorMapSwizzle,
                                 CUtensorMapL2promotion, CUtensorMapFloatOOBfill);

extern "C" void kernel_launch(void* const* d_in, const int* in_sizes, int n_in,
                              void* d_out, int out_size) {
    (void)in_sizes; (void)n_in; (void)out_size;
    const float* x = (const float*)d_in[0];
    const float* W = (const float*)d_in[1];
    float* out = (float*)d_out;

    void* xq_ptr = nullptr;
    void* ws_ptr = nullptr;
    cudaGetSymbolAddress(&xq_ptr, g_xq);
    cudaGetSymbolAddress(&ws_ptr, g_ws);

    quant_fused_kernel<<<QBLOCKS, 256>>>(x, W);

    PFN_tmEncode enc = nullptr;
    cudaDriverEntryPointQueryResult qr;
    cudaGetDriverEntryPointByVersion("cuTensorMapEncodeTiled", (void**)&enc, 12000,
                                     cudaEnableDefault, &qr);
    CUtensorMap mapA, mapB;
    {
        cuuint64_t dims[2] = {(cuuint64_t)KK, (cuuint64_t)MM};
        cuuint64_t strd[1] = {(cuuint64_t)KK * 2};
        cuuint32_t box[2]  = {BK, BM};
        cuuint32_t es[2]   = {1, 1};
        enc(&mapA, CU_TENSOR_MAP_DATA_TYPE_FLOAT16, 2, xq_ptr, dims, strd, box, es,
            CU_TENSOR_MAP_INTERLEAVE_NONE, CU_TENSOR_MAP_SWIZZLE_128B,
            CU_TENSOR_MAP_L2_PROMOTION_L2_128B, CU_TENSOR_MAP_FLOAT_OOB_FILL_NONE);
    }
    {
        cuuint64_t dims[2] = {(cuuint64_t)KK, (cuuint64_t)NN};
        cuuint64_t strd[1] = {(cuuint64_t)KK * 2};
        cuuint32_t box[2]  = {BK, BN};
        cuuint32_t es[2]   = {1, 1};
        enc(&mapB, CU_TENSOR_MAP_DATA_TYPE_FLOAT16, 2, ws_ptr, dims, strd, box, es,
            CU_TENSOR_MAP_INTERLEAVE_NONE, CU_TENSOR_MAP_SWIZZLE_128B,
            CU_TENSOR_MAP_L2_PROMOTION_L2_128B, CU_TENSOR_MAP_FLOAT_OOB_FILL_NONE);
    }

    cudaFuncSetAttribute(bitlinear_gemm, cudaFuncAttributeMaxDynamicSharedMemorySize, SMEM_TOTAL);
    bitlinear_gemm<<<dim3(NN / BN, MM / BM), 256, SMEM_TOTAL>>>(mapA, mapB, out);
}

// round 13
// speedup vs baseline: 1.1111x; 1.1111x over previous
#include <cuda.h>
#include <cuda_runtime.h>
#include <cuda_fp16.h>
#include <cstdint>

// ---------------- problem sizes ----------------
#define MM 8192
#define NN 4096
#define KK 4096
#define GRP 64

#define BM 128
#define BN 128
#define BK 64
#define NSTAGE 3
#define KITER (KK / BK)          // 64 tiles, consumed in 32 pairs

#define A_BYTES (BM * BK * 2)    // 16384
#define B_BYTES (BN * BK * 2)    // 16384
#define STG_BYTES (A_BYTES + B_BYTES)   // 32768

#define SM_ALPHA 0               /* 128 floats */
#define SM_BARS 512              /* NSTAGE full barriers, 8B each */
#define SM_TILE 1024
#define SMEM_TOTAL (SM_TILE + NSTAGE * STG_BYTES)   /* 99328 -> 2 CTAs/SM */

#define XBLOCKS 16384            /* quant blocks handling x */
#define QBLOCKS (XBLOCKS + NN)   /* + one block per W row */

// ---------------- scratch (no allocations allowed) ----------------
__device__ __align__(1024) __half g_xq[(size_t)MM * KK];   // 64 MB
__device__ __align__(1024) __half g_ws[(size_t)NN * KK];   // 32 MB
__device__ float g_alpha[NN];

// ---------------- PTX helpers (plain sm_90-level features only) ----------------
__device__ __forceinline__ uint32_t smem_u32(const void* p) {
    uint32_t a;
    asm("{ .reg .u64 t; cvta.to.shared.u64 t, %1; cvt.u32.u64 %0, t; }" : "=r"(a) : "l"(p));
    return a;
}
__device__ __forceinline__ void mbar_init(uint32_t a, uint32_t c) {
    asm volatile("mbarrier.init.shared.b64 [%0], %1;" :: "r"(a), "r"(c) : "memory");
}
__device__ __forceinline__ void mbar_expect(uint32_t a, uint32_t bytes) {
    asm volatile("mbarrier.arrive.expect_tx.shared.b64 _, [%0], %1;" :: "r"(a), "r"(bytes) : "memory");
}
__device__ __forceinline__ void mbar_wait(uint32_t a, uint32_t p) {
    asm volatile(
        "{\n\t.reg .pred P;\n\t"
        "WL%=:\n\t"
        "mbarrier.try_wait.parity.acquire.cta.shared::cta.b64 P, [%0], %1, 0x989680;\n\t"
        "@P bra.uni WD%=;\n\t"
        "bra.uni WL%=;\n\t"
        "WD%=:\n\t}"
        :: "r"(a), "r"(p) : "memory");
}
__device__ __forceinline__ void tma_load_2d(uint32_t smem_addr, const void* map,
                                            int cx, int cy, uint32_t mbar) {
    asm volatile(
        "cp.async.bulk.tensor.2d.shared::cta.global.tile.mbarrier::complete_tx::bytes "
        "[%0], [%1, {%2, %3}], [%4];"
        :: "r"(smem_addr), "l"(map), "r"(cx), "r"(cy), "r"(mbar) : "memory");
}
__device__ __forceinline__ void ldsm_x4(uint32_t addr, uint32_t* r) {
    asm volatile("ldmatrix.sync.aligned.m8n8.x4.shared.b16 {%0,%1,%2,%3}, [%4];"
                 : "=r"(r[0]), "=r"(r[1]), "=r"(r[2]), "=r"(r[3]) : "r"(addr));
}
__device__ __forceinline__ void mma16816(float* c, const uint32_t* a, const uint32_t* b) {
    asm volatile(
        "mma.sync.aligned.m16n8k16.row.col.f32.f16.f16.f32 "
        "{%0,%1,%2,%3}, {%4,%5,%6,%7}, {%8,%9}, {%0,%1,%2,%3};"
        : "+f"(c[0]), "+f"(c[1]), "+f"(c[2]), "+f"(c[3])
        : "r"(a[0]), "r"(a[1]), "r"(a[2]), "r"(a[3]), "r"(b[0]), "r"(b[1]));
}
// PDL primitives (sm_90 base PTX; passes compute_103 virtual arch)
__device__ __forceinline__ void pdl_trigger() {
    asm volatile("griddepcontrol.launch_dependents;" ::: "memory");
}
__device__ __forceinline__ void pdl_wait() {
    asm volatile("griddepcontrol.wait;" ::: "memory");
}

__device__ __forceinline__ float sgnf(float c) { return (c > 0.f) ? 1.f : ((c < 0.f) ? -1.f : 0.f); }
__device__ __forceinline__ float warp_sum(float v) {
#pragma unroll
    for (int o = 16; o > 0; o >>= 1) v += __shfl_xor_sync(0xFFFFFFFFu, v, o);
    return v;
}

// ---------------- fused quant kernel: x-groups (blocks < XBLOCKS) + W rows ----------------
__global__ void __launch_bounds__(256) quant_fused_kernel(const float* __restrict__ x,
                                                          const float* __restrict__ W) {
    pdl_trigger();
    if (blockIdx.x < XBLOCKS) {
        // ---- group-64 absmax fake-quant of x -> fp16 (8 threads/group, 8 floats/thread) ----
        uint32_t t = blockIdx.x * 256u + threadIdx.x;
        size_t base = (size_t)(t >> 3) * GRP + (size_t)(t & 7) * 8;
        float4 a = *reinterpret_cast<const float4*>(x + base);
        float4 b = *reinterpret_cast<const float4*>(x + base + 4);
        float am = fmaxf(fmaxf(fmaxf(fabsf(a.x), fabsf(a.y)), fmaxf(fabsf(a.z), fabsf(a.w))),
                         fmaxf(fmaxf(fabsf(b.x), fabsf(b.y)), fmaxf(fabsf(b.z), fabsf(b.w))));
        am = fmaxf(am, __shfl_xor_sync(0xFFFFFFFFu, am, 1));
        am = fmaxf(am, __shfl_xor_sync(0xFFFFFFFFu, am, 2));
        am = fmaxf(am, __shfl_xor_sync(0xFFFFFFFFu, am, 4));
        float s = fmaxf(am, 1e-8f);
        float inv = __fdividef(127.0f, s);
        float sc = s * (1.0f / 127.0f);
        __half2 h0 = __floats2half2_rn(rintf(a.x * inv) * sc, rintf(a.y * inv) * sc);
        __half2 h1 = __floats2half2_rn(rintf(a.z * inv) * sc, rintf(a.w * inv) * sc);
        __half2 h2 = __floats2half2_rn(rintf(b.x * inv) * sc, rintf(b.y * inv) * sc);
        __half2 h3 = __floats2half2_rn(rintf(b.z * inv) * sc, rintf(b.w * inv) * sc);
        uint4 u;
        u.x = *reinterpret_cast<uint32_t*>(&h0);
        u.y = *reinterpret_cast<uint32_t*>(&h1);
        u.z = *reinterpret_cast<uint32_t*>(&h2);
        u.w = *reinterpret_cast<uint32_t*>(&h3);
        *reinterpret_cast<uint4*>(g_xq + base) = u;
    } else {
        // ---- per-row W binarize (centered sign) + alpha ----
        const int row = blockIdx.x - XBLOCKS;
        const int tid = threadIdx.x;
        const float4* wr = reinterpret_cast<const float4*>(W + (size_t)row * KK);
        float4 v[4];
        float s = 0.f;
#pragma unroll
        for (int i = 0; i < 4; i++) {
            v[i] = wr[i * 256 + tid];
            s += (v[i].x + v[i].y) + (v[i].z + v[i].w);
        }
        __shared__ float red[8];
        s = warp_sum(s);
        if ((tid & 31) == 0) red[tid >> 5] = s;
        __syncthreads();
        float mean = (red[0] + red[1] + red[2] + red[3] +
                      red[4] + red[5] + red[6] + red[7]) * (1.0f / 4096.0f);
        __syncthreads();
        float sa = 0.f;
#pragma unroll
        for (int i = 0; i < 4; i++)
            sa += (fabsf(v[i].x - mean) + fabsf(v[i].y - mean)) +
                  (fabsf(v[i].z - mean) + fabsf(v[i].w - mean));
        sa = warp_sum(sa);
        if ((tid & 31) == 0) red[tid >> 5] = sa;
        __syncthreads();
        if (tid == 0)
            g_alpha[row] = (red[0] + red[1] + red[2] + red[3] +
                            red[4] + red[5] + red[6] + red[7]) * (1.0f / 4096.0f);
        __half* wrow = g_ws + (size_t)row * KK;
#pragma unroll
        for (int i = 0; i < 4; i++) {
            __half2 h0 = __floats2half2_rn(sgnf(v[i].x - mean), sgnf(v[i].y - mean));
            __half2 h1 = __floats2half2_rn(sgnf(v[i].z - mean), sgnf(v[i].w - mean));
            uint2 u;
            u.x = *reinterpret_cast<uint32_t*>(&h0);
            u.y = *reinterpret_cast<uint32_t*>(&h1);
            *reinterpret_cast<uint2*>(wrow + (size_t)(i * 256 + tid) * 4) = u;
        }
    }
}

// ---------------- kernel 3: TMA-pipelined mma.sync f16 GEMM, paired-sync ring + PDL ----------------
__global__ void __launch_bounds__(256, 2)
bitlinear_gemm(const __grid_constant__ CUtensorMap mapA,
               const __grid_constant__ CUtensorMap mapB,
               float* __restrict__ out) {
    extern __shared__ char smem[];
    const uint32_t sb = smem_u32(smem);
    const int tid = threadIdx.x;
    const int l = tid & 31;
    const int w = tid >> 5;
    const int wm = w & 3;       // 4 warps along M (32 rows each)
    const int wn = w >> 2;      // 2 warps along N (64 cols each)
    const int n0 = blockIdx.x * BN;
    const int m0 = blockIdx.y * BM;

    // ---- pre-sync prologue: runs concurrently with the quant kernel ----
    if (tid == 0) {
#pragma unroll
        for (int s = 0; s < NSTAGE; s++) mbar_init(sb + SM_BARS + 8 * s, 1);
    }

    // per-thread ldmatrix address precompute (SW128 swizzle XOR = (row&7)<<4)
    uint32_t aRow[2], aXor[2];
#pragma unroll
    for (int mi = 0; mi < 2; mi++) {
        int r = wm * 32 + mi * 16 + (l & 15);
        aRow[mi] = (uint32_t)r * 128u;
        aXor[mi] = (uint32_t)(r & 7) << 4;
    }
    const uint32_t akb = (uint32_t)(l >> 4) * 16u;
    const int g = l >> 3;
    uint32_t bRow[4], bXor[4];
#pragma unroll
    for (int nj4 = 0; nj4 < 4; nj4++) {
        int r = wn * 64 + nj4 * 16 + ((g >> 1) << 3) + (l & 7);
        bRow[nj4] = (uint32_t)r * 128u;
        bXor[nj4] = (uint32_t)(r & 7) << 4;
    }
    const uint32_t bkb = (uint32_t)(g & 1) * 16u;

    float acc[2][8][4];
#pragma unroll
    for (int mi = 0; mi < 2; mi++)
#pragma unroll
        for (int nj = 0; nj < 8; nj++)
#pragma unroll
            for (int c = 0; c < 4; c++) acc[mi][nj][c] = 0.f;

    // ---- wait for quant grid completion + memory visibility ----
    pdl_wait();

    if (tid < 128)
        reinterpret_cast<float*>(smem + SM_ALPHA)[tid] = g_alpha[n0 + tid];
    __syncthreads();   // mbar_init visible to all before TMA completes into them

    // prologue: fill all 3 stages with tiles 0,1,2
    if (tid == 0) {
#pragma unroll
        for (int t = 0; t < NSTAGE; t++) {
            mbar_expect(sb + SM_BARS + 8 * t, STG_BYTES);
            uint32_t dst = sb + SM_TILE + t * STG_BYTES;
            tma_load_2d(dst,           &mapA, t * BK, m0, sb + SM_BARS + 8 * t);
            tma_load_2d(dst + A_BYTES, &mapB, t * BK, n0, sb + SM_BARS + 8 * t);
        }
    }

    // consume tiles in pairs; staggered per-tile waits; one __syncthreads per pair
    for (int p = 0; p < KITER / 2; p++) {
#pragma unroll
        for (int h = 0; h < 2; h++) {
            const int t = 2 * p + h;
            const int st = t % NSTAGE;
            mbar_wait(sb + SM_BARS + 8 * st, (uint32_t)((t / NSTAGE) & 1));
            const uint32_t ab = sb + SM_TILE + st * STG_BYTES;
            const uint32_t bb = ab + A_BYTES;
#pragma unroll
            for (int ks = 0; ks < BK / 16; ks++) {
                uint32_t af[2][4], bf[4][4];
#pragma unroll
                for (int mi = 0; mi < 2; mi++)
                    ldsm_x4(ab + aRow[mi] + (((uint32_t)ks * 32u + akb) ^ aXor[mi]), af[mi]);
#pragma unroll
                for (int nj4 = 0; nj4 < 4; nj4++)
                    ldsm_x4(bb + bRow[nj4] + (((uint32_t)ks * 32u + bkb) ^ bXor[nj4]), bf[nj4]);
#pragma unroll
                for (int mi = 0; mi < 2; mi++)
#pragma unroll
                    for (int nj4 = 0; nj4 < 4; nj4++) {
                        mma16816(acc[mi][2 * nj4 + 0], af[mi], &bf[nj4][0]);
                        mma16816(acc[mi][2 * nj4 + 1], af[mi], &bf[nj4][2]);
                    }
            }
        }
        __syncthreads();   // stages of tiles 2p, 2p+1 now free
        if (tid == 0) {
#pragma unroll
            for (int h = 3; h <= 4; h++) {
                const int nt = 2 * p + h;       // tiles 2p+3, 2p+4
                if (nt < KITER) {
                    const int sn = nt % NSTAGE;
                    mbar_expect(sb + SM_BARS + 8 * sn, STG_BYTES);
                    uint32_t dst = sb + SM_TILE + sn * STG_BYTES;
                    tma_load_2d(dst,           &mapA, nt * BK, m0, sb + SM_BARS + 8 * sn);
                    tma_load_2d(dst + A_BYTES, &mapB, nt * BK, n0, sb + SM_BARS + 8 * sn);
                }
            }
        }
    }

    // ---- epilogue: scale by alpha[n], store fp32 ----
    const float* al = reinterpret_cast<const float*>(smem + SM_ALPHA);
    const int q = l >> 2, t4 = l & 3;
#pragma unroll
    for (int mi = 0; mi < 2; mi++) {
#pragma unroll
        for (int nj = 0; nj < 8; nj++) {
            const int nloc = wn * 64 + nj * 8 + t4 * 2;
            const float a0 = al[nloc], a1 = al[nloc + 1];
            const size_t r0 = (size_t)(m0 + wm * 32 + mi * 16 + q) * NN + n0 + nloc;
            float2 v0, v1;
            v0.x = acc[mi][nj][0] * a0; v0.y = acc[mi][nj][1] * a1;
            v1.x = acc[mi][nj][2] * a0; v1.y = acc[mi][nj][3] * a1;
            *reinterpret_cast<float2*>(out + r0) = v0;
            *reinterpret_cast<float2*>(out + r0 + 8 * NN) = v1;
        }
    }
}

// ---------------- host launch ----------------
typedef CUresult (*PFN_tmEncode)(CUtensorMap*, CUtensorMapDataType, cuuint32_t, void*,
                                 const cuuint64_t*, const cuuint64_t*, const cuuint32_t*,
                                 const cuuint32_t*, CUtensorMapInterleave, CUtensorMapSwizzle,
                                 CUtensorMapL2promotion, CUtensorMapFloatOOBfill);

extern "C" void kernel_launch(void* const* d_in, const int* in_sizes, int n_in,
                              void* d_out, int out_size) {
    (void)in_sizes; (void)n_in; (void)out_size;
    const float* x = (const float*)d_in[0];
    const float* W = (const float*)d_in[1];
    float* out = (float*)d_out;

    void* xq_ptr = nullptr;
    void* ws_ptr = nullptr;
    cudaGetSymbolAddress(&xq_ptr, g_xq);
    cudaGetSymbolAddress(&ws_ptr, g_ws);

    quant_fused_kernel<<<QBLOCKS, 256>>>(x, W);

    PFN_tmEncode enc = nullptr;
    cudaDriverEntryPointQueryResult qr;
    cudaGetDriverEntryPointByVersion("cuTensorMapEncodeTiled", (void**)&enc, 12000,
                                     cudaEnableDefault, &qr);
    CUtensorMap mapA, mapB;
    {
        cuuint64_t dims[2] = {(cuuint64_t)KK, (cuuint64_t)MM};
        cuuint64_t strd[1] = {(cuuint64_t)KK * 2};
        cuuint32_t box[2]  = {BK, BM};
        cuuint32_t es[2]   = {1, 1};
        enc(&mapA, CU_TENSOR_MAP_DATA_TYPE_FLOAT16, 2, xq_ptr, dims, strd, box, es,
            CU_TENSOR_MAP_INTERLEAVE_NONE, CU_TENSOR_MAP_SWIZZLE_128B,
            CU_TENSOR_MAP_L2_PROMOTION_L2_128B, CU_TENSOR_MAP_FLOAT_OOB_FILL_NONE);
    }
    {
        cuuint64_t dims[2] = {(cuuint64_t)KK, (cuuint64_t)NN};
        cuuint64_t strd[1] = {(cuuint64_t)KK * 2};
        cuuint32_t box[2]  = {BK, BN};
        cuuint32_t es[2]   = {1, 1};
        enc(&mapB, CU_TENSOR_MAP_DATA_TYPE_FLOAT16, 2, ws_ptr, dims, strd, box, es,
            CU_TENSOR_MAP_INTERLEAVE_NONE, CU_TENSOR_MAP_SWIZZLE_128B,
            CU_TENSOR_MAP_L2_PROMOTION_L2_128B, CU_TENSOR_MAP_FLOAT_OOB_FILL_NONE);
    }

    cudaFuncSetAttribute(bitlinear_gemm, cudaFuncAttributeMaxDynamicSharedMemorySize, SMEM_TOTAL);

    // launch GEMM with PDL: its pre-sync prologue overlaps the quant kernel
    cudaLaunchConfig_t cfg = {};
    cfg.gridDim = dim3(NN / BN, MM / BM);
    cfg.blockDim = dim3(256, 1, 1);
    cfg.dynamicSmemBytes = SMEM_TOTAL;
    cfg.stream = 0;
    cudaLaunchAttribute attrs[1];
    attrs[0].id = cudaLaunchAttributeProgrammaticStreamSerialization;
    attrs[0].val.programmaticStreamSerializationAllowed = 1;
    cfg.attrs = attrs;
    cfg.numAttrs = 1;
    cudaLaunchKernelEx(&cfg, bitlinear_gemm, mapA, mapB, out);
}

// round 14
// speedup vs baseline: 1.1117x; 1.0006x over previous
#include <cuda.h>
#include <cuda_runtime.h>
#include <cuda_fp16.h>
#include <cstdint>

// ---------------- problem sizes ----------------
#define MM 8192
#define NN 4096
#define KK 4096
#define GRP 64

#define BM 128
#define BN 128
#define BK 64
#define NSTAGE 3
#define KITER (KK / BK)          // 64 tiles, consumed in 32 pairs

#define A_BYTES (BM * BK * 2)    // 16384
#define B_BYTES (BN * BK * 2)    // 16384
#define STG_BYTES (A_BYTES + B_BYTES)   // 32768

#define SM_ALPHA 0               /* 128 floats */
#define SM_BARS 512              /* NSTAGE full barriers, 8B each */
#define SM_TILE 1024
#define SMEM_TOTAL (SM_TILE + NSTAGE * STG_BYTES)   /* 99328 -> 2 CTAs/SM */

#define XBLOCKS 8192             /* x quant blocks: 256 thr, 16 floats/thread */
#define QBLOCKS (XBLOCKS + NN)   /* + one block per W row */

// ---------------- scratch (no allocations allowed) ----------------
__device__ __align__(1024) __half g_xq[(size_t)MM * KK];   // 64 MB
__device__ __align__(1024) __half g_ws[(size_t)NN * KK];   // 32 MB
__device__ float g_alpha[NN];

// ---------------- PTX helpers (plain sm_90-level features only) ----------------
__device__ __forceinline__ uint32_t smem_u32(const void* p) {
    uint32_t a;
    asm("{ .reg .u64 t; cvta.to.shared.u64 t, %1; cvt.u32.u64 %0, t; }" : "=r"(a) : "l"(p));
    return a;
}
__device__ __forceinline__ void mbar_init(uint32_t a, uint32_t c) {
    asm volatile("mbarrier.init.shared.b64 [%0], %1;" :: "r"(a), "r"(c) : "memory");
}
__device__ __forceinline__ void mbar_expect(uint32_t a, uint32_t bytes) {
    asm volatile("mbarrier.arrive.expect_tx.shared.b64 _, [%0], %1;" :: "r"(a), "r"(bytes) : "memory");
}
__device__ __forceinline__ void mbar_wait(uint32_t a, uint32_t p) {
    asm volatile(
        "{\n\t.reg .pred P;\n\t"
        "WL%=:\n\t"
        "mbarrier.try_wait.parity.acquire.cta.shared::cta.b64 P, [%0], %1, 0x989680;\n\t"
        "@P bra.uni WD%=;\n\t"
        "bra.uni WL%=;\n\t"
        "WD%=:\n\t}"
        :: "r"(a), "r"(p) : "memory");
}
__device__ __forceinline__ void tma_load_2d(uint32_t smem_addr, const void* map,
                                            int cx, int cy, uint32_t mbar) {
    asm volatile(
        "cp.async.bulk.tensor.2d.shared::cta.global.tile.mbarrier::complete_tx::bytes "
        "[%0], [%1, {%2, %3}], [%4];"
        :: "r"(smem_addr), "l"(map), "r"(cx), "r"(cy), "r"(mbar) : "memory");
}
__device__ __forceinline__ void ldsm_x4(uint32_t addr, uint32_t* r) {
    asm volatile("ldmatrix.sync.aligned.m8n8.x4.shared.b16 {%0,%1,%2,%3}, [%4];"
                 : "=r"(r[0]), "=r"(r[1]), "=r"(r[2]), "=r"(r[3]) : "r"(addr));
}
__device__ __forceinline__ void mma16816(float* c, const uint32_t* a, const uint32_t* b) {
    asm volatile(
        "mma.sync.aligned.m16n8k16.row.col.f32.f16.f16.f32 "
        "{%0,%1,%2,%3}, {%4,%5,%6,%7}, {%8,%9}, {%0,%1,%2,%3};"
        : "+f"(c[0]), "+f"(c[1]), "+f"(c[2]), "+f"(c[3])
        : "r"(a[0]), "r"(a[1]), "r"(a[2]), "r"(a[3]), "r"(b[0]), "r"(b[1]));
}
// PDL primitives (sm_90 base PTX; passes compute_103 virtual arch)
__device__ __forceinline__ void pdl_trigger() {
    asm volatile("griddepcontrol.launch_dependents;" ::: "memory");
}
__device__ __forceinline__ void pdl_wait() {
    asm volatile("griddepcontrol.wait;" ::: "memory");
}

__device__ __forceinline__ float sgnf(float c) { return (c > 0.f) ? 1.f : ((c < 0.f) ? -1.f : 0.f); }
__device__ __forceinline__ float warp_sum(float v) {
#pragma unroll
    for (int o = 16; o > 0; o >>= 1) v += __shfl_xor_sync(0xFFFFFFFFu, v, o);
    return v;
}

// ---------------- fused quant kernel: x-groups (blocks < XBLOCKS) + W rows ----------------
__global__ void __launch_bounds__(256) quant_fused_kernel(const float* __restrict__ x,
                                                          const float* __restrict__ W) {
    pdl_trigger();
    if (blockIdx.x < XBLOCKS) {
        // ---- group-64 absmax fake-quant of x -> fp16 ----
        // 4 threads/group, 16 floats/thread: 4 front-batched LDG.128 (high MLP), 2 shfls.
        uint32_t t = blockIdx.x * 256u + threadIdx.x;
        size_t base = (size_t)(t >> 2) * GRP + (size_t)(t & 3) * 16;
        float4 v[4];
#pragma unroll
        for (int i = 0; i < 4; i++)
            v[i] = *reinterpret_cast<const float4*>(x + base + 4 * i);
        float am = 0.f;
#pragma unroll
        for (int i = 0; i < 4; i++)
            am = fmaxf(am, fmaxf(fmaxf(fabsf(v[i].x), fabsf(v[i].y)),
                                 fmaxf(fabsf(v[i].z), fabsf(v[i].w))));
        am = fmaxf(am, __shfl_xor_sync(0xFFFFFFFFu, am, 1));
        am = fmaxf(am, __shfl_xor_sync(0xFFFFFFFFu, am, 2));
        float s = fmaxf(am, 1e-8f);
        float inv = __fdividef(127.0f, s);
        float sc = s * (1.0f / 127.0f);
#pragma unroll
        for (int i = 0; i < 2; i++) {
            __half2 h0 = __floats2half2_rn(rintf(v[2*i].x * inv) * sc, rintf(v[2*i].y * inv) * sc);
            __half2 h1 = __floats2half2_rn(rintf(v[2*i].z * inv) * sc, rintf(v[2*i].w * inv) * sc);
            __half2 h2 = __floats2half2_rn(rintf(v[2*i+1].x * inv) * sc, rintf(v[2*i+1].y * inv) * sc);
            __half2 h3 = __floats2half2_rn(rintf(v[2*i+1].z * inv) * sc, rintf(v[2*i+1].w * inv) * sc);
            uint4 u;
            u.x = *reinterpret_cast<uint32_t*>(&h0);
            u.y = *reinterpret_cast<uint32_t*>(&h1);
            u.z = *reinterpret_cast<uint32_t*>(&h2);
            u.w = *reinterpret_cast<uint32_t*>(&h3);
            *reinterpret_cast<uint4*>(g_xq + base + 8 * i) = u;
        }
    } else {
        // ---- per-row W binarize (centered sign) + alpha ----
        const int row = blockIdx.x - XBLOCKS;
        const int tid = threadIdx.x;
        const float4* wr = reinterpret_cast<const float4*>(W + (size_t)row * KK);
        float4 v[4];
        float s = 0.f;
#pragma unroll
        for (int i = 0; i < 4; i++) {
            v[i] = wr[i * 256 + tid];
            s += (v[i].x + v[i].y) + (v[i].z + v[i].w);
        }
        __shared__ float red[8];
        s = warp_sum(s);
        if ((tid & 31) == 0) red[tid >> 5] = s;
        __syncthreads();
        float mean = (red[0] + red[1] + red[2] + red[3] +
                      red[4] + red[5] + red[6] + red[7]) * (1.0f / 4096.0f);
        __syncthreads();
        float sa = 0.f;
#pragma unroll
        for (int i = 0; i < 4; i++)
            sa += (fabsf(v[i].x - mean) + fabsf(v[i].y - mean)) +
                  (fabsf(v[i].z - mean) + fabsf(v[i].w - mean));
        sa = warp_sum(sa);
        if ((tid & 31) == 0) red[tid >> 5] = sa;
        __syncthreads();
        if (tid == 0)
            g_alpha[row] = (red[0] + red[1] + red[2] + red[3] +
                            red[4] + red[5] + red[6] + red[7]) * (1.0f / 4096.0f);
        __half* wrow = g_ws + (size_t)row * KK;
#pragma unroll
        for (int i = 0; i < 4; i++) {
            __half2 h0 = __floats2half2_rn(sgnf(v[i].x - mean), sgnf(v[i].y - mean));
            __half2 h1 = __floats2half2_rn(sgnf(v[i].z - mean), sgnf(v[i].w - mean));
            uint2 u;
            u.x = *reinterpret_cast<uint32_t*>(&h0);
            u.y = *reinterpret_cast<uint32_t*>(&h1);
            *reinterpret_cast<uint2*>(wrow + (size_t)(i * 256 + tid) * 4) = u;
        }
    }
}

// ---------------- kernel 3: TMA-pipelined mma.sync f16 GEMM, paired-sync ring + PDL ----------------
__global__ void __launch_bounds__(256, 2)
bitlinear_gemm(const __grid_constant__ CUtensorMap mapA,
               const __grid_constant__ CUtensorMap mapB,
               float* __restrict__ out) {
    extern __shared__ char smem[];
    const uint32_t sb = smem_u32(smem);
    const int tid = threadIdx.x;
    const int l = tid & 31;
    const int w = tid >> 5;
    const int wm = w & 3;       // 4 warps along M (32 rows each)
    const int wn = w >> 2;      // 2 warps along N (64 cols each)
    const int n0 = blockIdx.x * BN;
    const int m0 = blockIdx.y * BM;

    // ---- pre-sync prologue: runs concurrently with the quant kernel ----
    if (tid == 0) {
#pragma unroll
        for (int s = 0; s < NSTAGE; s++) mbar_init(sb + SM_BARS + 8 * s, 1);
    }

    // per-thread ldmatrix address precompute (SW128 swizzle XOR = (row&7)<<4)
    uint32_t aRow[2], aXor[2];
#pragma unroll
    for (int mi = 0; mi < 2; mi++) {
        int r = wm * 32 + mi * 16 + (l & 15);
        aRow[mi] = (uint32_t)r * 128u;
        aXor[mi] = (uint32_t)(r & 7) << 4;
    }
    const uint32_t akb = (uint32_t)(l >> 4) * 16u;
    const int g = l >> 3;
    uint32_t bRow[4], bXor[4];
#pragma unroll
    for (int nj4 = 0; nj4 < 4; nj4++) {
        int r = wn * 64 + nj4 * 16 + ((g >> 1) << 3) + (l & 7);
        bRow[nj4] = (uint32_t)r * 128u;
        bXor[nj4] = (uint32_t)(r & 7) << 4;
    }
    const uint32_t bkb = (uint32_t)(g & 1) * 16u;

    float acc[2][8][4];
#pragma unroll
    for (int mi = 0; mi < 2; mi++)
#pragma unroll
        for (int nj = 0; nj < 8; nj++)
#pragma unroll
            for (int c = 0; c < 4; c++) acc[mi][nj][c] = 0.f;

    // ---- wait for quant grid completion + memory visibility ----
    pdl_wait();

    if (tid < 128)
        reinterpret_cast<float*>(smem + SM_ALPHA)[tid] = g_alpha[n0 + tid];
    __syncthreads();   // mbar_init visible to all before TMA completes into them

    // prologue: fill all 3 stages with tiles 0,1,2
    if (tid == 0) {
#pragma unroll
        for (int t = 0; t < NSTAGE; t++) {
            mbar_expect(sb + SM_BARS + 8 * t, STG_BYTES);
            uint32_t dst = sb + SM_TILE + t * STG_BYTES;
            tma_load_2d(dst,           &mapA, t * BK, m0, sb + SM_BARS + 8 * t);
            tma_load_2d(dst + A_BYTES, &mapB, t * BK, n0, sb + SM_BARS + 8 * t);
        }
    }

    // consume tiles in pairs; staggered per-tile waits; one __syncthreads per pair
    for (int p = 0; p < KITER / 2; p++) {
#pragma unroll
        for (int h = 0; h < 2; h++) {
            const int t = 2 * p + h;
            const int st = t % NSTAGE;
            mbar_wait(sb + SM_BARS + 8 * st, (uint32_t)((t / NSTAGE) & 1));
            const uint32_t ab = sb + SM_TILE + st * STG_BYTES;
            const uint32_t bb = ab + A_BYTES;
#pragma unroll
            for (int ks = 0; ks < BK / 16; ks++) {
                uint32_t af[2][4], bf[4][4];
#pragma unroll
                for (int mi = 0; mi < 2; mi++)
                    ldsm_x4(ab + aRow[mi] + (((uint32_t)ks * 32u + akb) ^ aXor[mi]), af[mi]);
#pragma unroll
                for (int nj4 = 0; nj4 < 4; nj4++)
                    ldsm_x4(bb + bRow[nj4] + (((uint32_t)ks * 32u + bkb) ^ bXor[nj4]), bf[nj4]);
#pragma unroll
                for (int mi = 0; mi < 2; mi++)
#pragma unroll
                    for (int nj4 = 0; nj4 < 4; nj4++) {
                        mma16816(acc[mi][2 * nj4 + 0], af[mi], &bf[nj4][0]);
                        mma16816(acc[mi][2 * nj4 + 1], af[mi], &bf[nj4][2]);
                    }
            }
        }
        __syncthreads();   // stages of tiles 2p, 2p+1 now free
        if (tid == 0) {
#pragma unroll
            for (int h = 3; h <= 4; h++) {
                const int nt = 2 * p + h;       // tiles 2p+3, 2p+4
                if (nt < KITER) {
                    const int sn = nt % NSTAGE;
                    mbar_expect(sb + SM_BARS + 8 * sn, STG_BYTES);
                    uint32_t dst = sb + SM_TILE + sn * STG_BYTES;
                    tma_load_2d(dst,           &mapA, nt * BK, m0, sb + SM_BARS + 8 * sn);
                    tma_load_2d(dst + A_BYTES, &mapB, nt * BK, n0, sb + SM_BARS + 8 * sn);
                }
            }
        }
    }

    // ---- epilogue: scale by alpha[n], store fp32 ----
    const float* al = reinterpret_cast<const float*>(smem + SM_ALPHA);
    const int q = l >> 2, t4 = l & 3;
#pragma unroll
    for (int mi = 0; mi < 2; mi++) {
#pragma unroll
        for (int nj = 0; nj < 8; nj++) {
            const int nloc = wn * 64 + nj * 8 + t4 * 2;
            const float a0 = al[nloc], a1 = al[nloc + 1];
            const size_t r0 = (size_t)(m0 + wm * 32 + mi * 16 + q) * NN + n0 + nloc;
            float2 v0, v1;
            v0.x = acc[mi][nj][0] * a0; v0.y = acc[mi][nj][1] * a1;
            v1.x = acc[mi][nj][2] * a0; v1.y = acc[mi][nj][3] * a1;
            *reinterpret_cast<float2*>(out + r0) = v0;
            *reinterpret_cast<float2*>(out + r0 + 8 * NN) = v1;
        }
    }
}

// ---------------- host launch ----------------
typedef CUresult (*PFN_tmEncode)(CUtensorMap*, CUtensorMapDataType, cuuint32_t, void*,
                                 const cuuint64_t*, const cuuint64_t*, const cuuint32_t*,
                                 const cuuint32_t*, CUtensorMapInterleave, CUtensorMapSwizzle,
                                 CUtensorMapL2promotion, CUtensorMapFloatOOBfill);

extern "C" void kernel_launch(void* const* d_in, const int* in_sizes, int n_in,
                              void* d_out, int out_size) {
    (void)in_sizes; (void)n_in; (void)out_size;
    const float* x = (const float*)d_in[0];
    const float* W = (const float*)d_in[1];
    float* out = (float*)d_out;

    void* xq_ptr = nullptr;
    void* ws_ptr = nullptr;
    cudaGetSymbolAddress(&xq_ptr, g_xq);
    cudaGetSymbolAddress(&ws_ptr, g_ws);

    quant_fused_kernel<<<QBLOCKS, 256>>>(x, W);

    PFN_tmEncode enc = nullptr;
    cudaDriverEntryPointQueryResult qr;
    cudaGetDriverEntryPointByVersion("cuTensorMapEncodeTiled", (void**)&enc, 12000,
                                     cudaEnableDefault, &qr);
    CUtensorMap mapA, mapB;
    {
        cuuint64_t dims[2] = {(cuuint64_t)KK, (cuuint64_t)MM};
        cuuint64_t strd[1] = {(cuuint64_t)KK * 2};
        cuuint32_t box[2]  = {BK, BM};
        cuuint32_t es[2]   = {1, 1};
        enc(&mapA, CU_TENSOR_MAP_DATA_TYPE_FLOAT16, 2, xq_ptr, dims, strd, box, es,
            CU_TENSOR_MAP_INTERLEAVE_NONE, CU_TENSOR_MAP_SWIZZLE_128B,
            CU_TENSOR_MAP_L2_PROMOTION_L2_128B, CU_TENSOR_MAP_FLOAT_OOB_FILL_NONE);
    }
    {
        cuuint64_t dims[2] = {(cuuint64_t)KK, (cuuint64_t)NN};
        cuuint64_t strd[1] = {(cuuint64_t)KK * 2};
        cuuint32_t box[2]  = {BK, BN};
        cuuint32_t es[2]   = {1, 1};
        enc(&mapB, CU_TENSOR_MAP_DATA_TYPE_FLOAT16, 2, ws_ptr, dims, strd, box, es,
            CU_TENSOR_MAP_INTERLEAVE_NONE, CU_TENSOR_MAP_SWIZZLE_128B,
            CU_TENSOR_MAP_L2_PROMOTION_L2_128B, CU_TENSOR_MAP_FLOAT_OOB_FILL_NONE);
    }

    cudaFuncSetAttribute(bitlinear_gemm, cudaFuncAttributeMaxDynamicSharedMemorySize, SMEM_TOTAL);

    // launch GEMM with PDL: its pre-sync prologue overlaps the quant kernel
    cudaLaunchConfig_t cfg = {};
    cfg.gridDim = dim3(NN / BN, MM / BM);
    cfg.blockDim = dim3(256, 1, 1);
    cfg.dynamicSmemBytes = SMEM_TOTAL;
    cfg.stream = 0;
    cudaLaunchAttribute attrs[1];
    attrs[0].id = cudaLaunchAttributeProgrammaticStreamSerialization;
    attrs[0].val.programmaticStreamSerializationAllowed = 1;
    cfg.attrs = attrs;
    cfg.numAttrs = 1;
    cudaLaunchKernelEx(&cfg, bitlinear_gemm, mapA, mapB, out);
}

// round 15
// speedup vs baseline: 1.1134x; 1.0015x over previous
#include <cuda.h>
#include <cuda_runtime.h>
#include <cuda_fp16.h>
#include <cstdint>

// ---------------- problem sizes ----------------
#define MM 8192
#define NN 4096
#define KK 4096
#define GRP 64

#define BM 128
#define BN 128
#define BK 64
#define NSTAGE 3
#define KITER (KK / BK)          // 64 tiles, consumed in 32 pairs

#define A_BYTES (BM * BK * 2)    // 16384
#define B_BYTES (BN * BK * 2)    // 16384
#define STG_BYTES (A_BYTES + B_BYTES)   // 32768

#define SM_ALPHA 0               /* 128 floats */
#define SM_BARS 512              /* NSTAGE full barriers, 8B each */
#define SM_TILE 1024
#define SMEM_TOTAL (SM_TILE + NSTAGE * STG_BYTES)   /* 99328 -> 2 CTAs/SM */

#define XBLOCKS 16384            /* quant blocks handling x */
#define QBLOCKS (XBLOCKS + NN)   /* + one block per W row */

// ---------------- scratch (no allocations allowed) ----------------
__device__ __align__(1024) __half g_xq[(size_t)MM * KK];   // 64 MB
__device__ __align__(1024) __half g_ws[(size_t)NN * KK];   // 32 MB
__device__ float g_alpha[NN];

// ---------------- PTX helpers (plain sm_90-level features only) ----------------
__device__ __forceinline__ uint32_t smem_u32(const void* p) {
    uint32_t a;
    asm("{ .reg .u64 t; cvta.to.shared.u64 t, %1; cvt.u32.u64 %0, t; }" : "=r"(a) : "l"(p));
    return a;
}
__device__ __forceinline__ void mbar_init(uint32_t a, uint32_t c) {
    asm volatile("mbarrier.init.shared.b64 [%0], %1;" :: "r"(a), "r"(c) : "memory");
}
__device__ __forceinline__ void mbar_expect(uint32_t a, uint32_t bytes) {
    asm volatile("mbarrier.arrive.expect_tx.shared.b64 _, [%0], %1;" :: "r"(a), "r"(bytes) : "memory");
}
__device__ __forceinline__ void mbar_wait(uint32_t a, uint32_t p) {
    asm volatile(
        "{\n\t.reg .pred P;\n\t"
        "WL%=:\n\t"
        "mbarrier.try_wait.parity.acquire.cta.shared::cta.b64 P, [%0], %1, 0x989680;\n\t"
        "@P bra.uni WD%=;\n\t"
        "bra.uni WL%=;\n\t"
        "WD%=:\n\t}"
        :: "r"(a), "r"(p) : "memory");
}
__device__ __forceinline__ void tma_load_2d(uint32_t smem_addr, const void* map,
                                            int cx, int cy, uint32_t mbar) {
    asm volatile(
        "cp.async.bulk.tensor.2d.shared::cta.global.tile.mbarrier::complete_tx::bytes "
        "[%0], [%1, {%2, %3}], [%4];"
        :: "r"(smem_addr), "l"(map), "r"(cx), "r"(cy), "r"(mbar) : "memory");
}
__device__ __forceinline__ void ldsm_x4(uint32_t addr, uint32_t* r) {
    asm volatile("ldmatrix.sync.aligned.m8n8.x4.shared.b16 {%0,%1,%2,%3}, [%4];"
                 : "=r"(r[0]), "=r"(r[1]), "=r"(r[2]), "=r"(r[3]) : "r"(addr));
}
__device__ __forceinline__ void mma16816(float* c, const uint32_t* a, const uint32_t* b) {
    asm volatile(
        "mma.sync.aligned.m16n8k16.row.col.f32.f16.f16.f32 "
        "{%0,%1,%2,%3}, {%4,%5,%6,%7}, {%8,%9}, {%0,%1,%2,%3};"
        : "+f"(c[0]), "+f"(c[1]), "+f"(c[2]), "+f"(c[3])
        : "r"(a[0]), "r"(a[1]), "r"(a[2]), "r"(a[3]), "r"(b[0]), "r"(b[1]));
}
// PDL primitives (sm_90 base PTX; passes compute_103 virtual arch)
__device__ __forceinline__ void pdl_trigger() {
    asm volatile("griddepcontrol.launch_dependents;" ::: "memory");
}
__device__ __forceinline__ void pdl_wait() {
    asm volatile("griddepcontrol.wait;" ::: "memory");
}

__device__ __forceinline__ float sgnf(float c) { return (c > 0.f) ? 1.f : ((c < 0.f) ? -1.f : 0.f); }
__device__ __forceinline__ float warp_sum(float v) {
#pragma unroll
    for (int o = 16; o > 0; o >>= 1) v += __shfl_xor_sync(0xFFFFFFFFu, v, o);
    return v;
}

// ---------------- fused quant kernel: x-groups (blocks < XBLOCKS) + W rows ----------------
__global__ void __launch_bounds__(256) quant_fused_kernel(const float* __restrict__ x,
                                                          const float* __restrict__ W) {
    pdl_trigger();
    if (blockIdx.x < XBLOCKS) {
        // ---- group-64 absmax fake-quant of x -> fp16 (8 threads/group, 8 floats/thread) ----
        uint32_t t = blockIdx.x * 256u + threadIdx.x;
        size_t base = (size_t)(t >> 3) * GRP + (size_t)(t & 7) * 8;
        float4 a = *reinterpret_cast<const float4*>(x + base);
        float4 b = *reinterpret_cast<const float4*>(x + base + 4);
        float am = fmaxf(fmaxf(fmaxf(fabsf(a.x), fabsf(a.y)), fmaxf(fabsf(a.z), fabsf(a.w))),
                         fmaxf(fmaxf(fabsf(b.x), fabsf(b.y)), fmaxf(fabsf(b.z), fabsf(b.w))));
        am = fmaxf(am, __shfl_xor_sync(0xFFFFFFFFu, am, 1));
        am = fmaxf(am, __shfl_xor_sync(0xFFFFFFFFu, am, 2));
        am = fmaxf(am, __shfl_xor_sync(0xFFFFFFFFu, am, 4));
        float s = fmaxf(am, 1e-8f);
        float inv = __fdividef(127.0f, s);
        float sc = s * (1.0f / 127.0f);
        __half2 h0 = __floats2half2_rn(rintf(a.x * inv) * sc, rintf(a.y * inv) * sc);
        __half2 h1 = __floats2half2_rn(rintf(a.z * inv) * sc, rintf(a.w * inv) * sc);
        __half2 h2 = __floats2half2_rn(rintf(b.x * inv) * sc, rintf(b.y * inv) * sc);
        __half2 h3 = __floats2half2_rn(rintf(b.z * inv) * sc, rintf(b.w * inv) * sc);
        uint4 u;
        u.x = *reinterpret_cast<uint32_t*>(&h0);
        u.y = *reinterpret_cast<uint32_t*>(&h1);
        u.z = *reinterpret_cast<uint32_t*>(&h2);
        u.w = *reinterpret_cast<uint32_t*>(&h3);
        *reinterpret_cast<uint4*>(g_xq + base) = u;
    } else {
        // ---- per-row W binarize (centered sign) + alpha ----
        const int row = blockIdx.x - XBLOCKS;
        const int tid = threadIdx.x;
        const float4* wr = reinterpret_cast<const float4*>(W + (size_t)row * KK);
        float4 v[4];
        float s = 0.f;
#pragma unroll
        for (int i = 0; i < 4; i++) {
            v[i] = wr[i * 256 + tid];
            s += (v[i].x + v[i].y) + (v[i].z + v[i].w);
        }
        __shared__ float red[8];
        s = warp_sum(s);
        if ((tid & 31) == 0) red[tid >> 5] = s;
        __syncthreads();
        float mean = (red[0] + red[1] + red[2] + red[3] +
                      red[4] + red[5] + red[6] + red[7]) * (1.0f / 4096.0f);
        __syncthreads();
        float sa = 0.f;
#pragma unroll
        for (int i = 0; i < 4; i++)
            sa += (fabsf(v[i].x - mean) + fabsf(v[i].y - mean)) +
                  (fabsf(v[i].z - mean) + fabsf(v[i].w - mean));
        sa = warp_sum(sa);
        if ((tid & 31) == 0) red[tid >> 5] = sa;
        __syncthreads();
        if (tid == 0)
            g_alpha[row] = (red[0] + red[1] + red[2] + red[3] +
                            red[4] + red[5] + red[6] + red[7]) * (1.0f / 4096.0f);
        __half* wrow = g_ws + (size_t)row * KK;
#pragma unroll
        for (int i = 0; i < 4; i++) {
            __half2 h0 = __floats2half2_rn(sgnf(v[i].x - mean), sgnf(v[i].y - mean));
            __half2 h1 = __floats2half2_rn(sgnf(v[i].z - mean), sgnf(v[i].w - mean));
            uint2 u;
            u.x = *reinterpret_cast<uint32_t*>(&h0);
            u.y = *reinterpret_cast<uint32_t*>(&h1);
            *reinterpret_cast<uint2*>(wrow + (size_t)(i * 256 + tid) * 4) = u;
        }
    }
}

// ---------------- kernel 3: TMA-pipelined mma.sync f16 GEMM, paired-sync ring + PDL ----------------
__global__ void __launch_bounds__(256, 2)
bitlinear_gemm(const __grid_constant__ CUtensorMap mapA,
               const __grid_constant__ CUtensorMap mapB,
               float* __restrict__ out) {
    extern __shared__ char smem[];
    const uint32_t sb = smem_u32(smem);
    const int tid = threadIdx.x;
    const int l = tid & 31;
    const int w = tid >> 5;
    const int wm = w & 3;       // 4 warps along M (32 rows each)
    const int wn = w >> 2;      // 2 warps along N (64 cols each)
    const int n0 = blockIdx.x * BN;
    const int m0 = blockIdx.y * BM;

    // ---- pre-sync prologue: runs concurrently with the quant kernel ----
    if (tid == 0) {
#pragma unroll
        for (int s = 0; s < NSTAGE; s++) mbar_init(sb + SM_BARS + 8 * s, 1);
    }

    // per-thread ldmatrix address precompute (SW128 swizzle XOR = (row&7)<<4)
    uint32_t aRow[2], aXor[2];
#pragma unroll
    for (int mi = 0; mi < 2; mi++) {
        int r = wm * 32 + mi * 16 + (l & 15);
        aRow[mi] = (uint32_t)r * 128u;
        aXor[mi] = (uint32_t)(r & 7) << 4;
    }
    const uint32_t akb = (uint32_t)(l >> 4) * 16u;
    const int g = l >> 3;
    uint32_t bRow[4], bXor[4];
#pragma unroll
    for (int nj4 = 0; nj4 < 4; nj4++) {
        int r = wn * 64 + nj4 * 16 + ((g >> 1) << 3) + (l & 7);
        bRow[nj4] = (uint32_t)r * 128u;
        bXor[nj4] = (uint32_t)(r & 7) << 4;
    }
    const uint32_t bkb = (uint32_t)(g & 1) * 16u;

    float acc[2][8][4];
#pragma unroll
    for (int mi = 0; mi < 2; mi++)
#pragma unroll
        for (int nj = 0; nj < 8; nj++)
#pragma unroll
            for (int c = 0; c < 4; c++) acc[mi][nj][c] = 0.f;

    // ---- wait for quant grid completion + memory visibility ----
    pdl_wait();

    if (tid < 128)
        reinterpret_cast<float*>(smem + SM_ALPHA)[tid] = g_alpha[n0 + tid];
    __syncthreads();   // mbar_init visible to all before TMA completes into them

    // prologue: fill all 3 stages with tiles 0,1,2
    if (tid == 0) {
#pragma unroll
        for (int t = 0; t < NSTAGE; t++) {
            mbar_expect(sb + SM_BARS + 8 * t, STG_BYTES);
            uint32_t dst = sb + SM_TILE + t * STG_BYTES;
            tma_load_2d(dst,           &mapA, t * BK, m0, sb + SM_BARS + 8 * t);
            tma_load_2d(dst + A_BYTES, &mapB, t * BK, n0, sb + SM_BARS + 8 * t);
        }
    }

    // consume tiles in pairs; staggered per-tile waits; one __syncthreads per pair
    for (int p = 0; p < KITER / 2; p++) {
#pragma unroll
        for (int h = 0; h < 2; h++) {
            const int t = 2 * p + h;
            const int st = t % NSTAGE;
            mbar_wait(sb + SM_BARS + 8 * st, (uint32_t)((t / NSTAGE) & 1));
            const uint32_t ab = sb + SM_TILE + st * STG_BYTES;
            const uint32_t bb = ab + A_BYTES;
#pragma unroll
            for (int ks = 0; ks < BK / 16; ks++) {
                uint32_t af[2][4], bf[4][4];
#pragma unroll
                for (int mi = 0; mi < 2; mi++)
                    ldsm_x4(ab + aRow[mi] + (((uint32_t)ks * 32u + akb) ^ aXor[mi]), af[mi]);
#pragma unroll
                for (int nj4 = 0; nj4 < 4; nj4++)
                    ldsm_x4(bb + bRow[nj4] + (((uint32_t)ks * 32u + bkb) ^ bXor[nj4]), bf[nj4]);
#pragma unroll
                for (int mi = 0; mi < 2; mi++)
#pragma unroll
                    for (int nj4 = 0; nj4 < 4; nj4++) {
                        mma16816(acc[mi][2 * nj4 + 0], af[mi], &bf[nj4][0]);
                        mma16816(acc[mi][2 * nj4 + 1], af[mi], &bf[nj4][2]);
                    }
            }
        }
        __syncthreads();   // stages of tiles 2p, 2p+1 now free
        if (tid == 0) {
#pragma unroll
            for (int h = 3; h <= 4; h++) {
                const int nt = 2 * p + h;       // tiles 2p+3, 2p+4
                if (nt < KITER) {
                    const int sn = nt % NSTAGE;
                    mbar_expect(sb + SM_BARS + 8 * sn, STG_BYTES);
                    uint32_t dst = sb + SM_TILE + sn * STG_BYTES;
                    tma_load_2d(dst,           &mapA, nt * BK, m0, sb + SM_BARS + 8 * sn);
                    tma_load_2d(dst + A_BYTES, &mapB, nt * BK, n0, sb + SM_BARS + 8 * sn);
                }
            }
        }
    }

    // ---- epilogue: scale by alpha[n], store fp32 ----
    const float* al = reinterpret_cast<const float*>(smem + SM_ALPHA);
    const int q = l >> 2, t4 = l & 3;
#pragma unroll
    for (int mi = 0; mi < 2; mi++) {
#pragma unroll
        for (int nj = 0; nj < 8; nj++) {
            const int nloc = wn * 64 + nj * 8 + t4 * 2;
            const float a0 = al[nloc], a1 = al[nloc + 1];
            const size_t r0 = (size_t)(m0 + wm * 32 + mi * 16 + q) * NN + n0 + nloc;
            float2 v0, v1;
            v0.x = acc[mi][nj][0] * a0; v0.y = acc[mi][nj][1] * a1;
            v1.x = acc[mi][nj][2] * a0; v1.y = acc[mi][nj][3] * a1;
            *reinterpret_cast<float2*>(out + r0) = v0;
            *reinterpret_cast<float2*>(out + r0 + 8 * NN) = v1;
        }
    }
}

// ---------------- host launch ----------------
typedef CUresult (*PFN_tmEncode)(CUtensorMap*, CUtensorMapDataType, cuuint32_t, void*,
                                 const cuuint64_t*, const cuuint64_t*, const cuuint32_t*,
                                 const cuuint32_t*, CUtensorMapInterleave, CUtensorMapSwizzle,
                                 CUtensorMapL2promotion, CUtensorMapFloatOOBfill);

extern "C" void kernel_launch(void* const* d_in, const int* in_sizes, int n_in,
                              void* d_out, int out_size) {
    (void)in_sizes; (void)n_in; (void)out_size;
    const float* x = (const float*)d_in[0];
    const float* W = (const float*)d_in[1];
    float* out = (float*)d_out;

    void* xq_ptr = nullptr;
    void* ws_ptr = nullptr;
    cudaGetSymbolAddress(&xq_ptr, g_xq);
    cudaGetSymbolAddress(&ws_ptr, g_ws);

    quant_fused_kernel<<<QBLOCKS, 256>>>(x, W);

    PFN_tmEncode enc = nullptr;
    cudaDriverEntryPointQueryResult qr;
    cudaGetDriverEntryPointByVersion("cuTensorMapEncodeTiled", (void**)&enc, 12000,
                                     cudaEnableDefault, &qr);
    CUtensorMap mapA, mapB;
    {
        cuuint64_t dims[2] = {(cuuint64_t)KK, (cuuint64_t)MM};
        cuuint64_t strd[1] = {(cuuint64_t)KK * 2};
        cuuint32_t box[2]  = {BK, BM};
        cuuint32_t es[2]   = {1, 1};
        enc(&mapA, CU_TENSOR_MAP_DATA_TYPE_FLOAT16, 2, xq_ptr, dims, strd, box, es,
            CU_TENSOR_MAP_INTERLEAVE_NONE, CU_TENSOR_MAP_SWIZZLE_128B,
            CU_TENSOR_MAP_L2_PROMOTION_L2_256B, CU_TENSOR_MAP_FLOAT_OOB_FILL_NONE);
    }
    {
        cuuint64_t dims[2] = {(cuuint64_t)KK, (cuuint64_t)NN};
        cuuint64_t strd[1] = {(cuuint64_t)KK * 2};
        cuuint32_t box[2]  = {BK, BN};
        cuuint32_t es[2]   = {1, 1};
        enc(&mapB, CU_TENSOR_MAP_DATA_TYPE_FLOAT16, 2, ws_ptr, dims, strd, box, es,
            CU_TENSOR_MAP_INTERLEAVE_NONE, CU_TENSOR_MAP_SWIZZLE_128B,
            CU_TENSOR_MAP_L2_PROMOTION_L2_256B, CU_TENSOR_MAP_FLOAT_OOB_FILL_NONE);
    }

    cudaFuncSetAttribute(bitlinear_gemm, cudaFuncAttributeMaxDynamicSharedMemorySize, SMEM_TOTAL);

    // launch GEMM with PDL: its pre-sync prologue overlaps the quant kernel
    cudaLaunchConfig_t cfg = {};
    cfg.gridDim = dim3(NN / BN, MM / BM);
    cfg.blockDim = dim3(256, 1, 1);
    cfg.dynamicSmemBytes = SMEM_TOTAL;
    cfg.stream = 0;
    cudaLaunchAttribute attrs[1];
    attrs[0].id = cudaLaunchAttributeProgrammaticStreamSerialization;
    attrs[0].val.programmaticStreamSerializationAllowed = 1;
    cfg.attrs = attrs;
    cfg.numAttrs = 1;
    cudaLaunchKernelEx(&cfg, bitlinear_gemm, mapA, mapB, out);
}

// round 16
// speedup vs baseline: 1.1135x; 1.0001x over previous
#include <cuda.h>
#include <cuda_runtime.h>
#include <cuda_fp16.h>
#include <cstdint>

// ---------------- problem sizes ----------------
#define MM 8192
#define NN 4096
#define KK 4096
#define GRP 64

#define BM 128
#define BN 128
#define BK 64
#define NSTAGE 3
#define KITER (KK / BK)          // 64 tiles, consumed in 32 pairs

#define A_BYTES (BM * BK * 2)    // 16384
#define B_BYTES (BN * BK * 2)    // 16384
#define STG_BYTES (A_BYTES + B_BYTES)   // 32768

#define SM_ALPHA 0               /* 128 floats */
#define SM_BARS 512              /* NSTAGE full barriers, 8B each */
#define SM_TILE 1024
#define SMEM_TOTAL (SM_TILE + NSTAGE * STG_BYTES)   /* 99328 -> 2 CTAs/SM */

#define XBLOCKS 16384            /* quant blocks handling x */
#define QBLOCKS (XBLOCKS + NN)   /* + one block per W row */

// ---------------- scratch (no allocations allowed) ----------------
__device__ __align__(1024) __half g_xq[(size_t)MM * KK];   // 64 MB
__device__ __align__(1024) __half g_ws[(size_t)NN * KK];   // 32 MB
__device__ float g_alpha[NN];

// ---------------- PTX helpers (plain sm_90-level features only) ----------------
__device__ __forceinline__ uint32_t smem_u32(const void* p) {
    uint32_t a;
    asm("{ .reg .u64 t; cvta.to.shared.u64 t, %1; cvt.u32.u64 %0, t; }" : "=r"(a) : "l"(p));
    return a;
}
__device__ __forceinline__ void mbar_init(uint32_t a, uint32_t c) {
    asm volatile("mbarrier.init.shared.b64 [%0], %1;" :: "r"(a), "r"(c) : "memory");
}
__device__ __forceinline__ void mbar_expect(uint32_t a, uint32_t bytes) {
    asm volatile("mbarrier.arrive.expect_tx.shared.b64 _, [%0], %1;" :: "r"(a), "r"(bytes) : "memory");
}
__device__ __forceinline__ void mbar_wait(uint32_t a, uint32_t p) {
    asm volatile(
        "{\n\t.reg .pred P;\n\t"
        "WL%=:\n\t"
        "mbarrier.try_wait.parity.acquire.cta.shared::cta.b64 P, [%0], %1, 0x989680;\n\t"
        "@P bra.uni WD%=;\n\t"
        "bra.uni WL%=;\n\t"
        "WD%=:\n\t}"
        :: "r"(a), "r"(p) : "memory");
}
__device__ __forceinline__ void tma_load_2d(uint32_t smem_addr, const void* map,
                                            int cx, int cy, uint32_t mbar) {
    asm volatile(
        "cp.async.bulk.tensor.2d.shared::cta.global.tile.mbarrier::complete_tx::bytes "
        "[%0], [%1, {%2, %3}], [%4];"
        :: "r"(smem_addr), "l"(map), "r"(cx), "r"(cy), "r"(mbar) : "memory");
}
__device__ __forceinline__ void tma_prefetch(const void* map) {
    asm volatile("prefetch.tensormap [%0];" :: "l"(map));
}
__device__ __forceinline__ void ldsm_x4(uint32_t addr, uint32_t* r) {
    asm volatile("ldmatrix.sync.aligned.m8n8.x4.shared.b16 {%0,%1,%2,%3}, [%4];"
                 : "=r"(r[0]), "=r"(r[1]), "=r"(r[2]), "=r"(r[3]) : "r"(addr));
}
__device__ __forceinline__ void mma16816(float* c, const uint32_t* a, const uint32_t* b) {
    asm volatile(
        "mma.sync.aligned.m16n8k16.row.col.f32.f16.f16.f32 "
        "{%0,%1,%2,%3}, {%4,%5,%6,%7}, {%8,%9}, {%0,%1,%2,%3};"
        : "+f"(c[0]), "+f"(c[1]), "+f"(c[2]), "+f"(c[3])
        : "r"(a[0]), "r"(a[1]), "r"(a[2]), "r"(a[3]), "r"(b[0]), "r"(b[1]));
}
// PDL primitives (sm_90 base PTX; passes compute_103 virtual arch)
__device__ __forceinline__ void pdl_trigger() {
    asm volatile("griddepcontrol.launch_dependents;" ::: "memory");
}
__device__ __forceinline__ void pdl_wait() {
    asm volatile("griddepcontrol.wait;" ::: "memory");
}

__device__ __forceinline__ float sgnf(float c) { return (c > 0.f) ? 1.f : ((c < 0.f) ? -1.f : 0.f); }
__device__ __forceinline__ float warp_sum(float v) {
#pragma unroll
    for (int o = 16; o > 0; o >>= 1) v += __shfl_xor_sync(0xFFFFFFFFu, v, o);
    return v;
}

// ---------------- fused quant kernel: x-groups (blocks < XBLOCKS) + W rows ----------------
__global__ void __launch_bounds__(256) quant_fused_kernel(const float* __restrict__ x,
                                                          const float* __restrict__ W) {
    pdl_trigger();
    if (blockIdx.x < XBLOCKS) {
        // ---- group-64 absmax fake-quant of x -> fp16 (8 threads/group, 8 floats/thread) ----
        uint32_t t = blockIdx.x * 256u + threadIdx.x;
        size_t base = (size_t)(t >> 3) * GRP + (size_t)(t & 7) * 8;
        float4 a = *reinterpret_cast<const float4*>(x + base);
        float4 b = *reinterpret_cast<const float4*>(x + base + 4);
        float am = fmaxf(fmaxf(fmaxf(fabsf(a.x), fabsf(a.y)), fmaxf(fabsf(a.z), fabsf(a.w))),
                         fmaxf(fmaxf(fabsf(b.x), fabsf(b.y)), fmaxf(fabsf(b.z), fabsf(b.w))));
        am = fmaxf(am, __shfl_xor_sync(0xFFFFFFFFu, am, 1));
        am = fmaxf(am, __shfl_xor_sync(0xFFFFFFFFu, am, 2));
        am = fmaxf(am, __shfl_xor_sync(0xFFFFFFFFu, am, 4));
        float s = fmaxf(am, 1e-8f);
        float inv = __fdividef(127.0f, s);
        float sc = s * (1.0f / 127.0f);
        __half2 h0 = __floats2half2_rn(rintf(a.x * inv) * sc, rintf(a.y * inv) * sc);
        __half2 h1 = __floats2half2_rn(rintf(a.z * inv) * sc, rintf(a.w * inv) * sc);
        __half2 h2 = __floats2half2_rn(rintf(b.x * inv) * sc, rintf(b.y * inv) * sc);
        __half2 h3 = __floats2half2_rn(rintf(b.z * inv) * sc, rintf(b.w * inv) * sc);
        uint4 u;
        u.x = *reinterpret_cast<uint32_t*>(&h0);
        u.y = *reinterpret_cast<uint32_t*>(&h1);
        u.z = *reinterpret_cast<uint32_t*>(&h2);
        u.w = *reinterpret_cast<uint32_t*>(&h3);
        *reinterpret_cast<uint4*>(g_xq + base) = u;
    } else {
        // ---- per-row W binarize (centered sign) + alpha ----
        const int row = blockIdx.x - XBLOCKS;
        const int tid = threadIdx.x;
        const float4* wr = reinterpret_cast<const float4*>(W + (size_t)row * KK);
        float4 v[4];
        float s = 0.f;
#pragma unroll
        for (int i = 0; i < 4; i++) {
            v[i] = wr[i * 256 + tid];
            s += (v[i].x + v[i].y) + (v[i].z + v[i].w);
        }
        __shared__ float red[8];
        s = warp_sum(s);
        if ((tid & 31) == 0) red[tid >> 5] = s;
        __syncthreads();
        float mean = (red[0] + red[1] + red[2] + red[3] +
                      red[4] + red[5] + red[6] + red[7]) * (1.0f / 4096.0f);
        __syncthreads();
        float sa = 0.f;
#pragma unroll
        for (int i = 0; i < 4; i++)
            sa += (fabsf(v[i].x - mean) + fabsf(v[i].y - mean)) +
                  (fabsf(v[i].z - mean) + fabsf(v[i].w - mean));
        sa = warp_sum(sa);
        if ((tid & 31) == 0) red[tid >> 5] = sa;
        __syncthreads();
        if (tid == 0)
            g_alpha[row] = (red[0] + red[1] + red[2] + red[3] +
                            red[4] + red[5] + red[6] + red[7]) * (1.0f / 4096.0f);
        __half* wrow = g_ws + (size_t)row * KK;
#pragma unroll
        for (int i = 0; i < 4; i++) {
            __half2 h0 = __floats2half2_rn(sgnf(v[i].x - mean), sgnf(v[i].y - mean));
            __half2 h1 = __floats2half2_rn(sgnf(v[i].z - mean), sgnf(v[i].w - mean));
            uint2 u;
            u.x = *reinterpret_cast<uint32_t*>(&h0);
            u.y = *reinterpret_cast<uint32_t*>(&h1);
            *reinterpret_cast<uint2*>(wrow + (size_t)(i * 256 + tid) * 4) = u;
        }
    }
}

// ---------------- kernel 3: TMA-pipelined mma.sync f16 GEMM, paired-sync ring + PDL ----------------
__global__ void __launch_bounds__(256, 2)
bitlinear_gemm(const __grid_constant__ CUtensorMap mapA,
               const __grid_constant__ CUtensorMap mapB,
               float* __restrict__ out) {
    extern __shared__ char smem[];
    const uint32_t sb = smem_u32(smem);
    const int tid = threadIdx.x;
    const int l = tid & 31;
    const int w = tid >> 5;
    const int wm = w & 3;       // 4 warps along M (32 rows each)
    const int wn = w >> 2;      // 2 warps along N (64 cols each)
    const int n0 = blockIdx.x * BN;
    const int m0 = blockIdx.y * BM;

    // ---- pre-sync prologue: runs concurrently with the quant kernel ----
    if (tid == 0) {
#pragma unroll
        for (int s = 0; s < NSTAGE; s++) mbar_init(sb + SM_BARS + 8 * s, 1);
        // warm the tensormap descriptors while waiting on the quant grid
        tma_prefetch(&mapA);
        tma_prefetch(&mapB);
    }

    // per-thread ldmatrix address precompute (SW128 swizzle XOR = (row&7)<<4)
    uint32_t aRow[2], aXor[2];
#pragma unroll
    for (int mi = 0; mi < 2; mi++) {
        int r = wm * 32 + mi * 16 + (l & 15);
        aRow[mi] = (uint32_t)r * 128u;
        aXor[mi] = (uint32_t)(r & 7) << 4;
    }
    const uint32_t akb = (uint32_t)(l >> 4) * 16u;
    const int g = l >> 3;
    uint32_t bRow[4], bXor[4];
#pragma unroll
    for (int nj4 = 0; nj4 < 4; nj4++) {
        int r = wn * 64 + nj4 * 16 + ((g >> 1) << 3) + (l & 7);
        bRow[nj4] = (uint32_t)r * 128u;
        bXor[nj4] = (uint32_t)(r & 7) << 4;
    }
    const uint32_t bkb = (uint32_t)(g & 1) * 16u;

    float acc[2][8][4];
#pragma unroll
    for (int mi = 0; mi < 2; mi++)
#pragma unroll
        for (int nj = 0; nj < 8; nj++)
#pragma unroll
            for (int c = 0; c < 4; c++) acc[mi][nj][c] = 0.f;

    // ---- wait for quant grid completion + memory visibility ----
    pdl_wait();

    if (tid < 128)
        reinterpret_cast<float*>(smem + SM_ALPHA)[tid] = g_alpha[n0 + tid];
    __syncthreads();   // mbar_init visible to all before TMA completes into them

    // prologue: fill all 3 stages with tiles 0,1,2
    if (tid == 0) {
#pragma unroll
        for (int t = 0; t < NSTAGE; t++) {
            mbar_expect(sb + SM_BARS + 8 * t, STG_BYTES);
            uint32_t dst = sb + SM_TILE + t * STG_BYTES;
            tma_load_2d(dst,           &mapA, t * BK, m0, sb + SM_BARS + 8 * t);
            tma_load_2d(dst + A_BYTES, &mapB, t * BK, n0, sb + SM_BARS + 8 * t);
        }
    }

    // consume tiles in pairs; staggered per-tile waits; one __syncthreads per pair
    for (int p = 0; p < KITER / 2; p++) {
#pragma unroll
        for (int h = 0; h < 2; h++) {
            const int t = 2 * p + h;
            const int st = t % NSTAGE;
            mbar_wait(sb + SM_BARS + 8 * st, (uint32_t)((t / NSTAGE) & 1));
            const uint32_t ab = sb + SM_TILE + st * STG_BYTES;
            const uint32_t bb = ab + A_BYTES;
#pragma unroll
            for (int ks = 0; ks < BK / 16; ks++) {
                uint32_t af[2][4], bf[4][4];
#pragma unroll
                for (int mi = 0; mi < 2; mi++)
                    ldsm_x4(ab + aRow[mi] + (((uint32_t)ks * 32u + akb) ^ aXor[mi]), af[mi]);
#pragma unroll
                for (int nj4 = 0; nj4 < 4; nj4++)
                    ldsm_x4(bb + bRow[nj4] + (((uint32_t)ks * 32u + bkb) ^ bXor[nj4]), bf[nj4]);
#pragma unroll
                for (int mi = 0; mi < 2; mi++)
#pragma unroll
                    for (int nj4 = 0; nj4 < 4; nj4++) {
                        mma16816(acc[mi][2 * nj4 + 0], af[mi], &bf[nj4][0]);
                        mma16816(acc[mi][2 * nj4 + 1], af[mi], &bf[nj4][2]);
                    }
            }
        }
        __syncthreads();   // stages of tiles 2p, 2p+1 now free
        if (tid == 0) {
#pragma unroll
            for (int h = 3; h <= 4; h++) {
                const int nt = 2 * p + h;       // tiles 2p+3, 2p+4
                if (nt < KITER) {
                    const int sn = nt % NSTAGE;
                    mbar_expect(sb + SM_BARS + 8 * sn, STG_BYTES);
                    uint32_t dst = sb + SM_TILE + sn * STG_BYTES;
                    tma_load_2d(dst,           &mapA, nt * BK, m0, sb + SM_BARS + 8 * sn);
                    tma_load_2d(dst + A_BYTES, &mapB, nt * BK, n0, sb + SM_BARS + 8 * sn);
                }
            }
        }
    }

    // ---- epilogue: scale by alpha[n], store fp32 ----
    const float* al = reinterpret_cast<const float*>(smem + SM_ALPHA);
    const int q = l >> 2, t4 = l & 3;
#pragma unroll
    for (int mi = 0; mi < 2; mi++) {
#pragma unroll
        for (int nj = 0; nj < 8; nj++) {
            const int nloc = wn * 64 + nj * 8 + t4 * 2;
            const float a0 = al[nloc], a1 = al[nloc + 1];
            const size_t r0 = (size_t)(m0 + wm * 32 + mi * 16 + q) * NN + n0 + nloc;
            float2 v0, v1;
            v0.x = acc[mi][nj][0] * a0; v0.y = acc[mi][nj][1] * a1;
            v1.x = acc[mi][nj][2] * a0; v1.y = acc[mi][nj][3] * a1;
            *reinterpret_cast<float2*>(out + r0) = v0;
            *reinterpret_cast<float2*>(out + r0 + 8 * NN) = v1;
        }
    }
}

// ---------------- host launch ----------------
typedef CUresult (*PFN_tmEncode)(CUtensorMap*, CUtensorMapDataType, cuuint32_t, void*,
                                 const cuuint64_t*, const cuuint64_t*, const cuuint32_t*,
                                 const cuuint32_t*, CUtensorMapInterleave, CUtensorMapSwizzle,
                                 CUtensorMapL2promotion, CUtensorMapFloatOOBfill);

extern "C" void kernel_launch(void* const* d_in, const int* in_sizes, int n_in,
                              void* d_out, int out_size) {
    (void)in_sizes; (void)n_in; (void)out_size;
    const float* x = (const float*)d_in[0];
    const float* W = (const float*)d_in[1];
    float* out = (float*)d_out;

    void* xq_ptr = nullptr;
    void* ws_ptr = nullptr;
    cudaGetSymbolAddress(&xq_ptr, g_xq);
    cudaGetSymbolAddress(&ws_ptr, g_ws);

    quant_fused_kernel<<<QBLOCKS, 256>>>(x, W);

    PFN_tmEncode enc = nullptr;
    cudaDriverEntryPointQueryResult qr;
    cudaGetDriverEntryPointByVersion("cuTensorMapEncodeTiled", (void**)&enc, 12000,
                                     cudaEnableDefault, &qr);
    CUtensorMap mapA, mapB;
    {
        cuuint64_t dims[2] = {(cuuint64_t)KK, (cuuint64_t)MM};
        cuuint64_t strd[1] = {(cuuint64_t)KK * 2};
        cuuint32_t box[2]  = {BK, BM};
        cuuint32_t es[2]   = {1, 1};
        enc(&mapA, CU_TENSOR_MAP_DATA_TYPE_FLOAT16, 2, xq_ptr, dims, strd, box, es,
            CU_TENSOR_MAP_INTERLEAVE_NONE, CU_TENSOR_MAP_SWIZZLE_128B,
            CU_TENSOR_MAP_L2_PROMOTION_L2_256B, CU_TENSOR_MAP_FLOAT_OOB_FILL_NONE);
    }
    {
        cuuint64_t dims[2] = {(cuuint64_t)KK, (cuuint64_t)NN};
        cuuint64_t strd[1] = {(cuuint64_t)KK * 2};
        cuuint32_t box[2]  = {BK, BN};
        cuuint32_t es[2]   = {1, 1};
        enc(&mapB, CU_TENSOR_MAP_DATA_TYPE_FLOAT16, 2, ws_ptr, dims, strd, box, es,
            CU_TENSOR_MAP_INTERLEAVE_NONE, CU_TENSOR_MAP_SWIZZLE_128B,
            CU_TENSOR_MAP_L2_PROMOTION_L2_256B, CU_TENSOR_MAP_FLOAT_OOB_FILL_NONE);
    }

    cudaFuncSetAttribute(bitlinear_gemm, cudaFuncAttributeMaxDynamicSharedMemorySize, SMEM_TOTAL);

    // launch GEMM with PDL: its pre-sync prologue overlaps the quant kernel
    cudaLaunchConfig_t cfg = {};
    cfg.gridDim = dim3(NN / BN, MM / BM);
    cfg.blockDim = dim3(256, 1, 1);
    cfg.dynamicSmemBytes = SMEM_TOTAL;
    cfg.stream = 0;
    cudaLaunchAttribute attrs[1];
    attrs[0].id = cudaLaunchAttributeProgrammaticStreamSerialization;
    attrs[0].val.programmaticStreamSerializationAllowed = 1;
    cfg.attrs = attrs;
    cfg.numAttrs = 1;
    cudaLaunchKernelEx(&cfg, bitlinear_gemm, mapA, mapB, out);
}